// round 1
// baseline (speedup 1.0000x reference)
#include <cuda_runtime.h>
#include <math.h>

// ---------------------------------------------------------------------------
// Fused per-graph GNN: 5x TAGConv(K=2) + ReLU + gated softmax pooling.
// One CTA per graph (5000 CTAs, 256 threads). Everything in shared memory.
//
// TAGConv identity used:  concat(h, Ah, A2h) @ W = h@Wa + (Ah)@Wb + (A2h)@Wc
// where Wa/Wb/Wc are consecutive DIN-row blocks of W. This needs only two
// ping-pong feature buffers.
// ---------------------------------------------------------------------------

#define NODES   100
#define EDGES   400
#define NTHR    256
#define ST      76      // row stride in floats (>= max dim 74, float4-aligned)
#define ROWSPAD 112     // 16 thread-rows * 7 rows each

struct SmemLayout {
    float buf0[ROWSPAD * ST];
    float buf1[ROWSPAD * ST];
    float norm[128];
    float red[128];
    float gate[128];
    int   rowptr[104];
    int   cnt[128];          // also used as fill cursor
    unsigned short csr[EDGES];
};

// ---- propagation: out[v] = norm[v] * sum_{e: dst=v} norm[src_e] * in[src_e]
template <int D>
__device__ __forceinline__ void prop(const float* __restrict__ in,
                                     float* __restrict__ outb,
                                     const float* __restrict__ nrm,
                                     const int* __restrict__ rowptr,
                                     const unsigned short* __restrict__ csr,
                                     int tid) {
    constexpr int NCH = (D + 15) / 16;
    for (int task = tid; task < NODES * NCH; task += NTHR) {
        int v  = task / NCH;
        int ch = task - v * NCH;
        int c0 = ch * 16;
        int cw = (D - c0 < 16) ? (D - c0) : 16;
        float acc[16];
#pragma unroll
        for (int i = 0; i < 16; i++) acc[i] = 0.f;
        int e0 = rowptr[v], e1 = rowptr[v + 1];
        for (int e = e0; e < e1; e++) {
            int s = csr[e];
            float f = nrm[s];
            const float* row = in + s * ST + c0;
#pragma unroll
            for (int i = 0; i < 16; i++)
                if (i < cw) acc[i] += f * row[i];
        }
        float nv = nrm[v];
        float* o = outb + v * ST + c0;
#pragma unroll
        for (int i = 0; i < 16; i++)
            if (i < cw) o[i] = nv * acc[i];
    }
}

// ---- one GEMM pass: acc[r][j] += H[rows][k] * W[k][cols]   (W row-major DINxDOUT)
template <int DIN, int DOUT, int CPT>
__device__ __forceinline__ void gemm_pass(float acc[7][CPT],
                                          const float* __restrict__ H,
                                          const float* __restrict__ W,
                                          int trow, int tcol) {
#pragma unroll 2
    for (int k = 0; k < DIN; k++) {
        float a[7];
#pragma unroll
        for (int i = 0; i < 7; i++)
            a[i] = H[(trow * 7 + i) * ST + k];
#pragma unroll
        for (int j = 0; j < CPT; j++) {
            int c = tcol + 16 * j;
            if (c < DOUT) {
                float w = __ldg(W + k * DOUT + c);
#pragma unroll
                for (int i = 0; i < 7; i++) acc[i][j] += a[i] * w;
            }
        }
    }
}

// ---- one TAGConv layer (destroys bufIn, result in bufOut)
template <int DIN, int DOUT>
__device__ __forceinline__ void layer(float* bufIn, float* bufOut,
                                      const float* __restrict__ W,
                                      const float* __restrict__ B,
                                      SmemLayout* sm, int tid) {
    constexpr int CPT = (DOUT + 15) / 16;
    int trow = tid >> 4;
    int tcol = tid & 15;

    // U = A H  -> bufOut
    prop<DIN>(bufIn, bufOut, sm->norm, sm->rowptr, sm->csr, tid);
    __syncthreads();

    float acc[7][CPT];
#pragma unroll
    for (int i = 0; i < 7; i++)
#pragma unroll
        for (int j = 0; j < CPT; j++) acc[i][j] = 0.f;

    gemm_pass<DIN, DOUT, CPT>(acc, bufIn,  W,                  trow, tcol); // h @ Wa
    gemm_pass<DIN, DOUT, CPT>(acc, bufOut, W + DIN * DOUT,     trow, tcol); // U @ Wb
    __syncthreads();

    // V = A U -> bufIn  (H is dead now)
    prop<DIN>(bufOut, bufIn, sm->norm, sm->rowptr, sm->csr, tid);
    __syncthreads();

    gemm_pass<DIN, DOUT, CPT>(acc, bufIn, W + 2 * DIN * DOUT,  trow, tcol); // V @ Wc
    __syncthreads();

    // epilogue: bias + relu -> bufOut (U dead)
#pragma unroll
    for (int j = 0; j < CPT; j++) {
        int c = tcol + 16 * j;
        if (c < DOUT) {
            float bv = __ldg(B + c);
#pragma unroll
            for (int i = 0; i < 7; i++) {
                int r = trow * 7 + i;
                if (r < NODES)
                    bufOut[r * ST + c] = fmaxf(acc[i][j] + bv, 0.f);
            }
        }
    }
    __syncthreads();
}

__global__ void __launch_bounds__(NTHR)
gnn_fused_kernel(const float* __restrict__ x,
                 const int* __restrict__ src,
                 const int* __restrict__ dst,
                 const float* __restrict__ W0, const float* __restrict__ b0,
                 const float* __restrict__ W1, const float* __restrict__ b1,
                 const float* __restrict__ W2, const float* __restrict__ b2,
                 const float* __restrict__ W3, const float* __restrict__ b3,
                 const float* __restrict__ W4, const float* __restrict__ b4,
                 const float* __restrict__ gw, const float* __restrict__ gb,
                 float* __restrict__ out) {
    extern __shared__ char smem_raw[];
    SmemLayout* sm = reinterpret_cast<SmemLayout*>(smem_raw);
    const int tid = threadIdx.x;
    const int g   = blockIdx.x;

    float* A = sm->buf0;
    float* B = sm->buf1;

    // ---- load x tile (100 x 74, contiguous global) + zero pad rows 100..111
    {
        const float* xg = x + (size_t)g * (NODES * 74);
        for (int idx = tid; idx < NODES * 74; idx += NTHR) {
            int v = idx / 74;
            int c = idx - v * 74;
            A[v * ST + c] = xg[idx];
        }
        for (int idx = tid; idx < (ROWSPAD - NODES) * ST; idx += NTHR) {
            A[NODES * ST + idx] = 0.f;
            B[NODES * ST + idx] = 0.f;
        }
    }

    // ---- build per-graph CSR (by dst) + norm
    if (tid < 128) sm->cnt[tid] = 0;
    __syncthreads();
    const int* srcg = src + g * EDGES;
    const int* dstg = dst + g * EDGES;
    const int base = g * NODES;
    for (int e = tid; e < EDGES; e += NTHR) {
        int dl = dstg[e] - base;
        atomicAdd(&sm->cnt[dl], 1);
    }
    __syncthreads();
    if (tid < NODES)
        sm->norm[tid] = rsqrtf(fmaxf((float)sm->cnt[tid], 1.f));
    // inclusive scan over cnt[0..127] (Hillis-Steele)
    for (int off = 1; off < 128; off <<= 1) {
        int t = 0;
        if (tid < 128 && tid >= off) t = sm->cnt[tid - off];
        __syncthreads();
        if (tid < 128 && tid >= off) sm->cnt[tid] += t;
        __syncthreads();
    }
    if (tid == 0) sm->rowptr[0] = 0;
    if (tid < NODES) sm->rowptr[tid + 1] = sm->cnt[tid];
    __syncthreads();
    if (tid < NODES) sm->cnt[tid] = sm->rowptr[tid];   // fill cursors
    __syncthreads();
    for (int e = tid; e < EDGES; e += NTHR) {
        int sl = srcg[e] - base;
        int dl = dstg[e] - base;
        int pos = atomicAdd(&sm->cnt[dl], 1);
        sm->csr[pos] = (unsigned short)sl;
    }
    __syncthreads();

    // ---- 5 TAGConv layers (ping-pong buffers; each layer destroys its input)
    layer<74, 70>(A, B, W0, b0, sm, tid);
    layer<70, 65>(B, A, W1, b1, sm, tid);
    layer<65, 60>(A, B, W2, b2, sm, tid);
    layer<60, 55>(B, A, W3, b3, sm, tid);
    layer<55, 37>(A, B, W4, b4, sm, tid);
    float* H = B;   // final features: 100 x 37

    // ---- gate = H @ gate_w + gate_b
    float gval = -1e30f;
    if (tid < NODES) {
        float s = __ldg(gb);
#pragma unroll
        for (int c = 0; c < 37; c++)
            s += H[tid * ST + c] * __ldg(gw + c);
        sm->gate[tid] = s;
        gval = s;
    }
    if (tid < 128) sm->red[tid] = gval;
    __syncthreads();
    for (int s = 64; s > 0; s >>= 1) {
        if (tid < s) sm->red[tid] = fmaxf(sm->red[tid], sm->red[tid + s]);
        __syncthreads();
    }
    float gmax = sm->red[0];
    __syncthreads();

    float ev = 0.f;
    if (tid < NODES) {
        ev = expf(sm->gate[tid] - gmax);
        sm->gate[tid] = ev;
    }
    if (tid < 128) sm->red[tid] = ev;
    __syncthreads();
    for (int s = 64; s > 0; s >>= 1) {
        if (tid < s) sm->red[tid] += sm->red[tid + s];
        __syncthreads();
    }
    float Z = sm->red[0];

    // ---- pooled[c] = sum_v e_v * H[v][c] / Z
    if (tid < 37) {
        float a = 0.f;
        for (int v = 0; v < NODES; v++)
            a += sm->gate[v] * H[v * ST + tid];
        out[g * 37 + tid] = a / Z;
    }
}

extern "C" void kernel_launch(void* const* d_in, const int* in_sizes, int n_in,
                              void* d_out, int out_size) {
    const float* x   = (const float*)d_in[0];
    const int*   src = (const int*)d_in[1];
    const int*   dst = (const int*)d_in[2];
    // d_in[3] = graph_ids (implicit: node i -> graph i/100), unused
    const float* W0 = (const float*)d_in[4];
    const float* b0 = (const float*)d_in[5];
    const float* W1 = (const float*)d_in[6];
    const float* b1 = (const float*)d_in[7];
    const float* W2 = (const float*)d_in[8];
    const float* b2 = (const float*)d_in[9];
    const float* W3 = (const float*)d_in[10];
    const float* b3 = (const float*)d_in[11];
    const float* W4 = (const float*)d_in[12];
    const float* b4 = (const float*)d_in[13];
    const float* gw = (const float*)d_in[14];
    const float* gb = (const float*)d_in[15];
    float* out = (float*)d_out;

    const int smem_bytes = (int)sizeof(SmemLayout);
    cudaFuncSetAttribute(gnn_fused_kernel,
                         cudaFuncAttributeMaxDynamicSharedMemorySize,
                         smem_bytes);

    gnn_fused_kernel<<<5000, NTHR, smem_bytes>>>(
        x, src, dst,
        W0, b0, W1, b1, W2, b2, W3, b3, W4, b4,
        gw, gb, out);
}

// round 2
// speedup vs baseline: 1.4522x; 1.4522x over previous
#include <cuda_runtime.h>
#include <math.h>

// ---------------------------------------------------------------------------
// Fused per-graph GNN: 5x TAGConv(K=2) + ReLU + gated softmax pooling.
// One CTA per graph (5000 CTAs, 256 threads). All features in shared memory.
//
// R2: GEMM rebuilt around packed fp32x2 FMA (fma.rn.f32x2) with
//  - weights repacked+zero-padded by a prep kernel so column-pair LDG.64 and
//    k-quad LDS.128 need no bounds checks,
//  - zero-pad invariant on feature buffers (pad cols & rows always 0).
// ---------------------------------------------------------------------------

#define NODES   100
#define EDGES   400
#define NTHR    256
#define ST      76      // row stride in floats (multiple of 4)
#define ROWSPAD 112     // 16 thread-rows * 7 rows each

typedef unsigned long long ull;

__device__ __forceinline__ ull ffma2(ull a, ull b, ull c) {
    ull d;
    asm("fma.rn.f32x2 %0, %1, %2, %3;" : "=l"(d) : "l"(a), "l"(b), "l"(c));
    return d;
}
__device__ __forceinline__ ull pack2(float x, float y) {
    ull d;
    asm("mov.b64 %0, {%1, %2};" : "=l"(d) : "f"(x), "f"(y));
    return d;
}
__device__ __forceinline__ void unpack2(ull v, float& x, float& y) {
    asm("mov.b64 {%0, %1}, %2;" : "=f"(x), "=f"(y) : "l"(v));
}

// ---- padded weight scratch ------------------------------------------------
// layer l: [3][DINP][DP] row-major, zero-filled pads.
// DIN  = 74,70,65,60,55 ; DINP = 76,72,68,60,56
// DOUT = 70,65,60,55,37 ; DP   = 72,68,60,56,40
// sizes 3*DINP*DP: 16416,14688,12240,10080,6720  -> total 60144 floats
__device__ float g_Wpad[60144];

__global__ void prep_weights(const float* W0, const float* W1, const float* W2,
                             const float* W3, const float* W4) {
    const int DIN[5]  = {74, 70, 65, 60, 55};
    const int DINP[5] = {76, 72, 68, 60, 56};
    const int DOUT[5] = {70, 65, 60, 55, 37};
    const int DP[5]   = {72, 68, 60, 56, 40};
    const int OFF[6]  = {0, 16416, 31104, 43344, 53424, 60144};
    const float* Ws[5] = {W0, W1, W2, W3, W4};

    for (int idx = blockIdx.x * blockDim.x + threadIdx.x; idx < 60144;
         idx += gridDim.x * blockDim.x) {
        int l = 0;
        while (idx >= OFF[l + 1]) l++;
        int rel = idx - OFF[l];
        int blk = rel / (DINP[l] * DP[l]);
        int r2  = rel - blk * (DINP[l] * DP[l]);
        int k   = r2 / DP[l];
        int c   = r2 - k * DP[l];
        float v = 0.f;
        if (k < DIN[l] && c < DOUT[l])
            v = Ws[l][(blk * DIN[l] + k) * DOUT[l] + c];
        g_Wpad[idx] = v;
    }
}

struct SmemLayout {
    float buf0[ROWSPAD * ST];
    float buf1[ROWSPAD * ST];
    float norm[128];
    float red[128];
    float gate[128];
    int   rowptr[104];
    int   cnt[128];
    unsigned short csr[EDGES];
};

// ---- propagation over padded width: out[v][0..DINP) = n_v * sum n_s in[s]
// pad cols of `in` are zero => pad cols of `out` stay zero.
template <int DINP>
__device__ __forceinline__ void prop(const float* __restrict__ in,
                                     float* __restrict__ outb,
                                     const float* __restrict__ nrm,
                                     const int* __restrict__ rowptr,
                                     const unsigned short* __restrict__ csr,
                                     int tid) {
    constexpr int NQ = DINP / 4;
    for (int task = tid; task < NODES * NQ; task += NTHR) {
        int v  = task / NQ;
        int q  = task - v * NQ;
        int c0 = q * 4;
        float4 acc = make_float4(0.f, 0.f, 0.f, 0.f);
        int e0 = rowptr[v], e1 = rowptr[v + 1];
        for (int e = e0; e < e1; e++) {
            int s = csr[e];
            float f = nrm[s];
            float4 r = *reinterpret_cast<const float4*>(in + s * ST + c0);
            acc.x += f * r.x; acc.y += f * r.y;
            acc.z += f * r.z; acc.w += f * r.w;
        }
        float nv = nrm[v];
        acc.x *= nv; acc.y *= nv; acc.z *= nv; acc.w *= nv;
        *reinterpret_cast<float4*>(outb + v * ST + c0) = acc;
    }
}

// ---- one GEMM pass with packed f32x2: acc[row][slab] over column pairs.
template <int DINP, int DP, int SLABS>
__device__ __forceinline__ void gemm_pass(ull acc[7][SLABS],
                                          const float* __restrict__ H,
                                          const float* __restrict__ Wp,
                                          int trow, int tcol) {
    constexpr int PAIRS = DP / 2;
    const float* hb = H + trow * 7 * ST;
    int  off[SLABS];
    bool ok[SLABS];
#pragma unroll
    for (int s = 0; s < SLABS; s++) {
        int p = s * 16 + tcol;
        off[s] = 2 * p;
        ok[s]  = (p < PAIRS);
    }
#pragma unroll 2
    for (int k0 = 0; k0 < DINP; k0 += 4) {
        float4 a4[7];
#pragma unroll
        for (int i = 0; i < 7; i++)
            a4[i] = *reinterpret_cast<const float4*>(hb + i * ST + k0);
#pragma unroll
        for (int kk = 0; kk < 4; kk++) {
            const float* wrow = Wp + (k0 + kk) * DP;
            ull w[SLABS];
#pragma unroll
            for (int s = 0; s < SLABS; s++)
                w[s] = ok[s] ? __ldg(reinterpret_cast<const ull*>(wrow + off[s]))
                             : 0ull;
#pragma unroll
            for (int i = 0; i < 7; i++) {
                float av = (kk == 0) ? a4[i].x : (kk == 1) ? a4[i].y
                         : (kk == 2) ? a4[i].z : a4[i].w;
                ull aa = pack2(av, av);
#pragma unroll
                for (int s = 0; s < SLABS; s++)
                    acc[i][s] = ffma2(aa, w[s], acc[i][s]);
            }
        }
    }
}

// ---- one TAGConv layer (destroys bufIn, result in bufOut, pads zeroed)
template <int DINP, int DOUT, int DP, int SLABS>
__device__ __forceinline__ void layer(float* bufIn, float* bufOut,
                                      const float* __restrict__ Wp,
                                      const float* __restrict__ B,
                                      SmemLayout* sm, int tid) {
    int trow = tid >> 4;
    int tcol = tid & 15;

    // U = A h -> bufOut
    prop<DINP>(bufIn, bufOut, sm->norm, sm->rowptr, sm->csr, tid);
    __syncthreads();

    ull acc[7][SLABS];
#pragma unroll
    for (int i = 0; i < 7; i++)
#pragma unroll
        for (int s = 0; s < SLABS; s++) acc[i][s] = 0ull;

    gemm_pass<DINP, DP, SLABS>(acc, bufIn,  Wp,                 trow, tcol); // h@Wa
    gemm_pass<DINP, DP, SLABS>(acc, bufOut, Wp + DINP * DP,     trow, tcol); // U@Wb
    __syncthreads();

    // V = A U -> bufIn  (h dead)
    prop<DINP>(bufOut, bufIn, sm->norm, sm->rowptr, sm->csr, tid);
    __syncthreads();

    gemm_pass<DINP, DP, SLABS>(acc, bufIn, Wp + 2 * DINP * DP,  trow, tcol); // V@Wc
    __syncthreads();

    // epilogue: bias + relu -> bufOut; write zeros into pad cols [DOUT, DP)
#pragma unroll
    for (int s = 0; s < SLABS; s++) {
        int c = 2 * (s * 16 + tcol);
        if (c < DP) {
            float b0 = (c     < DOUT) ? __ldg(B + c)     : 0.f;
            float b1 = (c + 1 < DOUT) ? __ldg(B + c + 1) : 0.f;
#pragma unroll
            for (int i = 0; i < 7; i++) {
                int r = trow * 7 + i;
                if (r < NODES) {
                    float lo, hi;
                    unpack2(acc[i][s], lo, hi);
                    float v0 = (c     < DOUT) ? fmaxf(lo + b0, 0.f) : 0.f;
                    float v1 = (c + 1 < DOUT) ? fmaxf(hi + b1, 0.f) : 0.f;
                    *reinterpret_cast<float2*>(bufOut + r * ST + c) =
                        make_float2(v0, v1);
                }
            }
        }
    }
    __syncthreads();
}

__global__ void __launch_bounds__(NTHR, 2)
gnn_fused_kernel(const float* __restrict__ x,
                 const int* __restrict__ src,
                 const int* __restrict__ dst,
                 const float* __restrict__ b0, const float* __restrict__ b1,
                 const float* __restrict__ b2, const float* __restrict__ b3,
                 const float* __restrict__ b4,
                 const float* __restrict__ gw, const float* __restrict__ gb,
                 float* __restrict__ out) {
    extern __shared__ char smem_raw[];
    SmemLayout* sm = reinterpret_cast<SmemLayout*>(smem_raw);
    const int tid = threadIdx.x;
    const int g   = blockIdx.x;

    float* A = sm->buf0;
    float* B = sm->buf1;

    // ---- zero both buffers entirely (pad invariant), then load x
    {
        float4* z = reinterpret_cast<float4*>(sm->buf0);
        const int nq = 2 * ROWSPAD * ST / 4;   // buf0+buf1 contiguous
        for (int i = tid; i < nq; i += NTHR)
            z[i] = make_float4(0.f, 0.f, 0.f, 0.f);
    }
    if (tid < 128) sm->cnt[tid] = 0;
    __syncthreads();
    {
        const float* xg = x + (size_t)g * (NODES * 74);
        for (int idx = tid; idx < NODES * 74; idx += NTHR) {
            int v = idx / 74;
            int c = idx - v * 74;
            A[v * ST + c] = xg[idx];
        }
    }

    // ---- build per-graph CSR (by dst) + norm
    const int* srcg = src + g * EDGES;
    const int* dstg = dst + g * EDGES;
    const int base = g * NODES;
    for (int e = tid; e < EDGES; e += NTHR) {
        int dl = dstg[e] - base;
        atomicAdd(&sm->cnt[dl], 1);
    }
    __syncthreads();
    if (tid < NODES)
        sm->norm[tid] = rsqrtf(fmaxf((float)sm->cnt[tid], 1.f));
    for (int off = 1; off < 128; off <<= 1) {       // inclusive scan
        int t = 0;
        if (tid < 128 && tid >= off) t = sm->cnt[tid - off];
        __syncthreads();
        if (tid < 128 && tid >= off) sm->cnt[tid] += t;
        __syncthreads();
    }
    if (tid == 0) sm->rowptr[0] = 0;
    if (tid < NODES) sm->rowptr[tid + 1] = sm->cnt[tid];
    __syncthreads();
    if (tid < NODES) sm->cnt[tid] = sm->rowptr[tid];
    __syncthreads();
    for (int e = tid; e < EDGES; e += NTHR) {
        int sl = srcg[e] - base;
        int dl = dstg[e] - base;
        int pos = atomicAdd(&sm->cnt[dl], 1);
        sm->csr[pos] = (unsigned short)sl;
    }
    __syncthreads();

    // ---- 5 TAGConv layers
    //            DINP DOUT DP  SLABS  (weight block offsets in g_Wpad)
    layer<76, 70, 72, 3>(A, B, g_Wpad +     0, b0, sm, tid);
    layer<72, 65, 68, 3>(B, A, g_Wpad + 16416, b1, sm, tid);
    layer<68, 60, 60, 2>(A, B, g_Wpad + 31104, b2, sm, tid);
    layer<60, 55, 56, 2>(B, A, g_Wpad + 43344, b3, sm, tid);
    layer<56, 37, 40, 2>(A, B, g_Wpad + 53424, b4, sm, tid);
    float* H = B;   // final features: 100 x 37

    // ---- gate = H @ gate_w + gate_b ; softmax over graph; pooled sum
    float gval = -1e30f;
    if (tid < NODES) {
        float s = __ldg(gb);
#pragma unroll
        for (int c = 0; c < 37; c++)
            s += H[tid * ST + c] * __ldg(gw + c);
        sm->gate[tid] = s;
        gval = s;
    }
    if (tid < 128) sm->red[tid] = gval;
    __syncthreads();
    for (int s = 64; s > 0; s >>= 1) {
        if (tid < s) sm->red[tid] = fmaxf(sm->red[tid], sm->red[tid + s]);
        __syncthreads();
    }
    float gmax = sm->red[0];
    __syncthreads();

    float ev = 0.f;
    if (tid < NODES) {
        ev = expf(sm->gate[tid] - gmax);
        sm->gate[tid] = ev;
    }
    if (tid < 128) sm->red[tid] = ev;
    __syncthreads();
    for (int s = 64; s > 0; s >>= 1) {
        if (tid < s) sm->red[tid] += sm->red[tid + s];
        __syncthreads();
    }
    float Z = sm->red[0];

    if (tid < 37) {
        float a = 0.f;
        for (int v = 0; v < NODES; v++)
            a += sm->gate[v] * H[v * ST + tid];
        out[g * 37 + tid] = a / Z;
    }
}

extern "C" void kernel_launch(void* const* d_in, const int* in_sizes, int n_in,
                              void* d_out, int out_size) {
    const float* x   = (const float*)d_in[0];
    const int*   src = (const int*)d_in[1];
    const int*   dst = (const int*)d_in[2];
    const float* W0 = (const float*)d_in[4];
    const float* b0 = (const float*)d_in[5];
    const float* W1 = (const float*)d_in[6];
    const float* b1 = (const float*)d_in[7];
    const float* W2 = (const float*)d_in[8];
    const float* b2 = (const float*)d_in[9];
    const float* W3 = (const float*)d_in[10];
    const float* b3 = (const float*)d_in[11];
    const float* W4 = (const float*)d_in[12];
    const float* b4 = (const float*)d_in[13];
    const float* gw = (const float*)d_in[14];
    const float* gb = (const float*)d_in[15];
    float* out = (float*)d_out;

    prep_weights<<<60, 256>>>(W0, W1, W2, W3, W4);

    const int smem_bytes = (int)sizeof(SmemLayout);
    cudaFuncSetAttribute(gnn_fused_kernel,
                         cudaFuncAttributeMaxDynamicSharedMemorySize,
                         smem_bytes);
    gnn_fused_kernel<<<5000, NTHR, smem_bytes>>>(
        x, src, dst,
        b0, b1, b2, b3, b4,
        gw, gb, out);
}